// round 11
// baseline (speedup 1.0000x reference)
#include <cuda_runtime.h>
#include <cuda_fp16.h>
#include <cstdint>
#include <cstddef>

#define NNODES 30000
#define NEDGES 300000
#define DIN    256
#define DH     128
#define DOUT   64
#define LH     6
#define JKW    (DH * (LH + 1))   // 896
#define NB     ((NNODES + 255) / 256)   // 118 scan blocks
#define FEATB  7500                     // NNODES*DIN/4/256: feats-convert blocks

// ---------------- scratch (device globals: no allocs allowed) ----------------
__device__ __half g_feat16[(size_t)NNODES * DIN];
__device__ __half g_m16[(size_t)NNODES * DH];
__device__ __half g_jk16[(size_t)NNODES * JKW];
__device__ __half g_p16[(size_t)NNODES * DOUT];
__device__ float g_iso[NNODES], g_isi[NNODES];
__device__ int   g_cin[NNODES], g_cout[NNODES];
__device__ int   g_rp[NNODES + 1];
__device__ int   g_bsum[128];        // lookback flags (memset 0 each launch)
__device__ int   g_binc[128];        // lookback inclusive prefixes
__device__ int   g_cur[NNODES];
__device__ int   g_csrc[NEDGES];
// fp16 transposed weights, [N][K] each: W0t 128x256 | Wht 6x128x128 | WoutT 64x896
#define W0T_OFF   0
#define WHT_OFF   32768
#define WOUT_OFF  131072
__device__ __half g_w16[188416];

// ---------------- prep: feats fp32->fp16 + weights fp32->fp16 transposed ----
__global__ __launch_bounds__(256) void k_prep(
    const float* __restrict__ feats, const float* __restrict__ W0,
    const float* __restrict__ Wh, const float* __restrict__ Wout)
{
    int b = blockIdx.x;
    if (b < FEATB) {
        int i = b * 256 + threadIdx.x;
        float4 v = ((const float4*)feats)[i];
        ((__half2*)g_feat16)[2 * i]     = __floats2half2_rn(v.x, v.y);
        ((__half2*)g_feat16)[2 * i + 1] = __floats2half2_rn(v.z, v.w);
        return;
    }
    // weight transpose: 32x32 tiles
    __shared__ float sh[32][33];
    int bid = b - FEATB;
    const float* S; __half* D; int K, N, tk, tn;
    if (bid < 32)       { S = W0;   D = g_w16 + W0T_OFF;  K = 256; N = 128; tk = bid >> 2; tn = bid & 3; }
    else if (bid < 128) { int l = (bid - 32) >> 4, t2 = (bid - 32) & 15;
                          S = Wh + l * 16384; D = g_w16 + WHT_OFF + l * 16384;
                          K = 128; N = 128; tk = t2 >> 2; tn = t2 & 3; }
    else                { int t2 = bid - 128;
                          S = Wout; D = g_w16 + WOUT_OFF; K = 896; N = 64; tk = t2 >> 1; tn = t2 & 1; }
    int tx = threadIdx.x & 31, ty = threadIdx.x >> 5;   // 32 x 8
#pragma unroll
    for (int j = 0; j < 4; j++)
        sh[ty + j * 8][tx] = S[(size_t)(tk * 32 + ty + j * 8) * N + tn * 32 + tx];
    __syncthreads();
#pragma unroll
    for (int j = 0; j < 4; j++)
        D[(size_t)(tn * 32 + ty + j * 8) * K + tk * 32 + tx] = __float2half(sh[tx][ty + j * 8]);
}

// ---------------- CSR build ----------------
__global__ void k_hist(const int* __restrict__ src, const int* __restrict__ dst) {
    int e = blockIdx.x * blockDim.x + threadIdx.x;
    if (e < NEDGES) {
        atomicAdd(&g_cin[dst[e]], 1);
        atomicAdd(&g_cout[src[e]], 1);
    }
}

// fused scan (chained decoupled lookback) + rp/cursor/rsqrt
__global__ __launch_bounds__(256) void k_scanF() {
    __shared__ int sh[256];
    __shared__ int soff;
    int t = threadIdx.x, b = blockIdx.x;
    int i = b * 256 + t;
    int cin = (i < NNODES) ? g_cin[i] : 0;
    sh[t] = cin;
    __syncthreads();
    for (int o = 1; o < 256; o <<= 1) {
        int u = (t >= o) ? sh[t - o] : 0;
        __syncthreads();
        sh[t] += u;
        __syncthreads();
    }
    int li = sh[t];
    if (t == 0) {
        int off = 0;
        if (b > 0) {
            while (atomicAdd(&g_bsum[b - 1], 0) == 0) { }
            off = g_binc[b - 1];
        }
        g_binc[b] = off + sh[255];
        __threadfence();
        atomicExch(&g_bsum[b], 1);
        soff = off;
    }
    __syncthreads();
    if (i < NNODES) {
        int inc = li + soff;
        g_rp[i + 1] = inc;
        if (i == 0) g_rp[0] = 0;
        g_cur[i] = inc - cin;
        g_iso[i] = rsqrtf((float)max(g_cout[i], 1));
        g_isi[i] = rsqrtf((float)max(cin, 1));
    }
}

__global__ void k_fill(const int* __restrict__ src, const int* __restrict__ dst) {
    int e = blockIdx.x * blockDim.x + threadIdx.x;
    if (e < NEDGES) {
        int pos = atomicAdd(&g_cur[dst[e]], 1);
        g_csrc[pos] = src[e];
    }
}

// ---------------- CSR aggregation, width 128 (fp16 in/out, fp32 math) -------
__global__ __launch_bounds__(256) void k_agg128(
    const __half* __restrict__ x,
    const float* __restrict__ bias,
    __half* __restrict__ out, int ldo)
{
    int w = (int)((blockIdx.x * 256u + threadIdx.x) >> 5);
    int lane = threadIdx.x & 31;
    if (w >= NNODES) return;
    int beg = g_rp[w], end = g_rp[w + 1];

    float4 acc = make_float4(0.f, 0.f, 0.f, 0.f);
    int e = beg;
    for (; e + 4 <= end; e += 4) {
        int s0 = g_csrc[e], s1 = g_csrc[e + 1], s2 = g_csrc[e + 2], s3 = g_csrc[e + 3];
        float2 r0 = __ldg((const float2*)(x + (size_t)s0 * DH) + lane);
        float2 r1 = __ldg((const float2*)(x + (size_t)s1 * DH) + lane);
        float2 r2 = __ldg((const float2*)(x + (size_t)s2 * DH) + lane);
        float2 r3 = __ldg((const float2*)(x + (size_t)s3 * DH) + lane);
        float c0 = g_iso[s0], c1 = g_iso[s1], c2 = g_iso[s2], c3 = g_iso[s3];
        float2 a0 = __half22float2(*(__half2*)&r0.x), b0 = __half22float2(*(__half2*)&r0.y);
        float2 a1 = __half22float2(*(__half2*)&r1.x), b1 = __half22float2(*(__half2*)&r1.y);
        float2 a2 = __half22float2(*(__half2*)&r2.x), b2 = __half22float2(*(__half2*)&r2.y);
        float2 a3 = __half22float2(*(__half2*)&r3.x), b3 = __half22float2(*(__half2*)&r3.y);
        acc.x += a0.x * c0 + a1.x * c1 + a2.x * c2 + a3.x * c3;
        acc.y += a0.y * c0 + a1.y * c1 + a2.y * c2 + a3.y * c3;
        acc.z += b0.x * c0 + b1.x * c1 + b2.x * c2 + b3.x * c3;
        acc.w += b0.y * c0 + b1.y * c1 + b2.y * c2 + b3.y * c3;
    }
    for (; e < end; e++) {
        int s = g_csrc[e];
        float2 r = __ldg((const float2*)(x + (size_t)s * DH) + lane);
        float c = g_iso[s];
        float2 a = __half22float2(*(__half2*)&r.x), b = __half22float2(*(__half2*)&r.y);
        acc.x += a.x * c; acc.y += a.y * c; acc.z += b.x * c; acc.w += b.y * c;
    }

    float si = g_isi[w];
    float4 b = ((const float4*)bias)[lane];
    float vx = fmaxf(acc.x * si + b.x, 0.f);
    float vy = fmaxf(acc.y * si + b.y, 0.f);
    float vz = fmaxf(acc.z * si + b.z, 0.f);
    float vw = fmaxf(acc.w * si + b.w, 0.f);
    __half2* orow = (__half2*)(out + (size_t)w * ldo);
    orow[2 * lane]     = __floats2half2_rn(vx, vy);
    orow[2 * lane + 1] = __floats2half2_rn(vz, vw);
}

__global__ __launch_bounds__(256) void k_agg64(
    const __half* __restrict__ x,
    const float* __restrict__ bias,
    float* __restrict__ out)
{
    int w = (int)((blockIdx.x * 256u + threadIdx.x) >> 5);
    int lane = threadIdx.x & 31;
    if (w >= NNODES) return;
    int beg = g_rp[w], end = g_rp[w + 1];

    float2 acc = make_float2(0.f, 0.f);
    int e = beg;
    for (; e + 4 <= end; e += 4) {
        int s0 = g_csrc[e], s1 = g_csrc[e + 1], s2 = g_csrc[e + 2], s3 = g_csrc[e + 3];
        unsigned u0 = __ldg((const unsigned*)(x + (size_t)s0 * DOUT) + lane);
        unsigned u1 = __ldg((const unsigned*)(x + (size_t)s1 * DOUT) + lane);
        unsigned u2 = __ldg((const unsigned*)(x + (size_t)s2 * DOUT) + lane);
        unsigned u3 = __ldg((const unsigned*)(x + (size_t)s3 * DOUT) + lane);
        float2 f0 = __half22float2(*(__half2*)&u0);
        float2 f1 = __half22float2(*(__half2*)&u1);
        float2 f2 = __half22float2(*(__half2*)&u2);
        float2 f3 = __half22float2(*(__half2*)&u3);
        acc.x += f0.x + f1.x + f2.x + f3.x;
        acc.y += f0.y + f1.y + f2.y + f3.y;
    }
    for (; e < end; e++) {
        int s = g_csrc[e];
        unsigned u = __ldg((const unsigned*)(x + (size_t)s * DOUT) + lane);
        float2 f = __half22float2(*(__half2*)&u);
        acc.x += f.x; acc.y += f.y;
    }
    float2 b = ((const float2*)bias)[lane];
    ((float2*)(out + (size_t)w * DOUT))[lane] = make_float2(acc.x + b.x, acc.y + b.y);
}

// -------- fp16 HMMA GEMM (m16n8k16), cp.async 3-stage pipeline ---------------
__device__ __forceinline__ void mma_f16(float* c, const unsigned* a, const unsigned* b) {
    asm volatile(
        "mma.sync.aligned.m16n8k16.row.col.f32.f16.f16.f32 "
        "{%0,%1,%2,%3}, {%4,%5,%6,%7}, {%8,%9}, {%0,%1,%2,%3};"
        : "+f"(c[0]), "+f"(c[1]), "+f"(c[2]), "+f"(c[3])
        : "r"(a[0]), "r"(a[1]), "r"(a[2]), "r"(a[3]), "r"(b[0]), "r"(b[1]));
}

__device__ __forceinline__ void cpa16(uint32_t dst, const void* src, int sz) {
    asm volatile("cp.async.cg.shared.global [%0], [%1], 16, %2;"
                 :: "r"(dst), "l"(src), "r"(sz) : "memory");
}
__device__ __forceinline__ void cpa_commit() {
    asm volatile("cp.async.commit_group;" ::: "memory");
}
template <int Nw>
__device__ __forceinline__ void cpa_wait() {
    asm volatile("cp.async.wait_group %0;" :: "n"(Nw) : "memory");
}

// C[M, BN] = A[M, K] @ Bt^T;  A fp16 [M][lda], Bt fp16 [BN][K] (K contiguous), C fp16.
template <int BM, int BN, int BK, int WM, int WN, int STAGES>
__global__ __launch_bounds__(256) void k_gemm_h16(
    const __half* __restrict__ A, int lda, int M, int K,
    const __half* __restrict__ Bt,
    __half* __restrict__ C, int ldc)
{
    constexpr int ASH = BK + 8;    // halves; 80B row stride -> conflict-free frags
    constexpr int BSH = BK + 8;
    extern __shared__ char smraw[];
    __half* Asm = (__half*)smraw;                                   // STAGES*BM*ASH
    __half* Bsm = (__half*)(smraw + (size_t)STAGES * BM * ASH * 2); // STAGES*BN*BSH
    const uint32_t sA = (uint32_t)__cvta_generic_to_shared(Asm);
    const uint32_t sB = (uint32_t)__cvta_generic_to_shared(Bsm);

    constexpr int WARPS_N = BN / WN;
    static_assert((BM / WM) * WARPS_N == 8, "8 warps");
    constexpr int MT = WM / 16, NT = WN / 8;
    constexpr int KC = BK / 8;                  // 16B half-chunks per row
    constexpr int A_PT = BM * KC / 256;
    constexpr int B_PT = BN * KC / 256;

    const int tid = threadIdx.x;
    const int wid = tid >> 5, lane = tid & 31;
    const int wn = wid % WARPS_N, wm = wid / WARPS_N;
    const int g = lane >> 2, t = lane & 3;
    const int row0 = blockIdx.x * BM;
    const int S = K / BK;

    auto prefetch = [&](int s, int slot) {
        const int k0 = s * BK;
#pragma unroll
        for (int i = 0; i < A_PT; i++) {
            int id = tid + i * 256;
            int r = id / KC, q = id % KC;
            int gr = row0 + r;
            uint32_t d = sA + ((slot * BM + r) * ASH + q * 8) * 2;
            cpa16(d, A + (size_t)gr * lda + k0 + q * 8, (gr < M) ? 16 : 0);
        }
#pragma unroll
        for (int i = 0; i < B_PT; i++) {
            int id = tid + i * 256;
            int r = id / KC, q = id % KC;
            uint32_t d = sB + ((slot * BN + r) * BSH + q * 8) * 2;
            cpa16(d, Bt + (size_t)r * K + k0 + q * 8, 16);
        }
        cpa_commit();
    };

    float acc[MT][NT][4] = {};

#pragma unroll
    for (int s = 0; s < STAGES - 1; s++) prefetch(s, s);

#pragma unroll 1
    for (int s = 0; s < S; s++) {
        cpa_wait<STAGES - 2>();
        __syncthreads();

        int sn = s + STAGES - 1;
        if (sn < S) prefetch(sn, sn % STAGES);
        else        cpa_commit();

        const int slot = s % STAGES;
        const __half* Aslab = Asm + (size_t)slot * BM * ASH;
        const __half* Bslab = Bsm + (size_t)slot * BN * BSH;
#pragma unroll
        for (int ks = 0; ks < BK / 16; ks++) {
            unsigned a[MT][4], b[NT][2];
#pragma unroll
            for (int mt = 0; mt < MT; mt++) {
                const __half* ap = &Aslab[(wm * WM + mt * 16 + g) * ASH + ks * 16 + 2 * t];
                a[mt][0] = *(const unsigned*)(ap);
                a[mt][1] = *(const unsigned*)(ap + 8 * ASH);
                a[mt][2] = *(const unsigned*)(ap + 8);
                a[mt][3] = *(const unsigned*)(ap + 8 * ASH + 8);
            }
#pragma unroll
            for (int nt = 0; nt < NT; nt++) {
                const __half* bp = &Bslab[(wn * WN + nt * 8 + g) * BSH + ks * 16 + 2 * t];
                b[nt][0] = *(const unsigned*)(bp);
                b[nt][1] = *(const unsigned*)(bp + 8);
            }
#pragma unroll
            for (int mt = 0; mt < MT; mt++)
#pragma unroll
                for (int nt = 0; nt < NT; nt++)
                    mma_f16(acc[mt][nt], a[mt], b[nt]);
        }
    }

    // epilogue: half2 stores (bias/relu live in the agg kernels)
#pragma unroll
    for (int mt = 0; mt < MT; mt++) {
#pragma unroll
        for (int nt = 0; nt < NT; nt++) {
            int n = wn * WN + nt * 8 + 2 * t;
            int r0 = row0 + wm * WM + mt * 16 + g;
            if (r0 < M)
                *(__half2*)(C + (size_t)r0 * ldc + n) =
                    __floats2half2_rn(acc[mt][nt][0], acc[mt][nt][1]);
            int r1 = r0 + 8;
            if (r1 < M)
                *(__half2*)(C + (size_t)r1 * ldc + n) =
                    __floats2half2_rn(acc[mt][nt][2], acc[mt][nt][3]);
        }
    }
}

// ---------------- launch ----------------
extern "C" void kernel_launch(void* const* d_in, const int* in_sizes, int n_in,
                              void* d_out, int out_size)
{
    const float* feats = (const float*)d_in[0];
    const int*   src   = (const int*)d_in[1];
    const int*   dst   = (const int*)d_in[2];
    const float* W0    = (const float*)d_in[3];
    const float* b0    = (const float*)d_in[4];
    const float* Wh    = (const float*)d_in[5];
    const float* bh    = (const float*)d_in[6];
    const float* Wout  = (const float*)d_in[7];
    const float* bout  = (const float*)d_in[8];
    float* out = (float*)d_out;

    __half *f16, *m, *jk, *p, *w16;
    int *cin, *cout, *bsum;
    cudaGetSymbolAddress((void**)&f16,  g_feat16);
    cudaGetSymbolAddress((void**)&m,    g_m16);
    cudaGetSymbolAddress((void**)&jk,   g_jk16);
    cudaGetSymbolAddress((void**)&p,    g_p16);
    cudaGetSymbolAddress((void**)&w16,  g_w16);
    cudaGetSymbolAddress((void**)&cin,  g_cin);
    cudaGetSymbolAddress((void**)&cout, g_cout);
    cudaGetSymbolAddress((void**)&bsum, g_bsum);

    // dynamic smem: STAGES * (BM + BN) * (BK+8) * 2 bytes
    const int SM128 = 3 * (128 + 128) * 40 * 2;   // 61440
    const int SM64  = 3 * (128 + 64)  * 40 * 2;   // 46080
    cudaFuncSetAttribute((const void*)k_gemm_h16<128, 128, 32, 64, 32, 3>,
                         cudaFuncAttributeMaxDynamicSharedMemorySize, SM128);
    cudaFuncSetAttribute((const void*)k_gemm_h16<128, 64, 32, 32, 32, 3>,
                         cudaFuncAttributeMaxDynamicSharedMemorySize, SM64);

    const int T = 256;
    const int eb = (NEDGES + T - 1) / T;
    const int agg_blocks = (NNODES * 32 + T - 1) / T;
    const int gemm_blocks = (NNODES + 127) / 128;   // 235

    // CSR build + fp16 prep
    cudaMemsetAsync(cin,  0, NNODES * sizeof(int));
    cudaMemsetAsync(cout, 0, NNODES * sizeof(int));
    cudaMemsetAsync(bsum, 0, 128 * sizeof(int));
    k_prep<<<FEATB + 184, T>>>(feats, W0, Wh, Wout);
    k_hist<<<eb, T>>>(src, dst);
    k_scanF<<<NB, T>>>();
    k_fill<<<eb, T>>>(src, dst);

    // layer 0 (GEMM-first: project feats, then aggregate at width 128)
    k_gemm_h16<128, 128, 32, 64, 32, 3><<<gemm_blocks, T, SM128>>>(
        f16, DIN, NNODES, DIN, w16 + W0T_OFF, m, DH);
    k_agg128<<<agg_blocks, T>>>(m, b0, jk, JKW);

    // hidden layers 1..6
    for (int l = 0; l < LH; l++) {
        k_gemm_h16<128, 128, 32, 64, 32, 3><<<gemm_blocks, T, SM128>>>(
            jk + (size_t)l * DH, JKW, NNODES, DH, w16 + WHT_OFF + (size_t)l * DH * DH, m, DH);
        k_agg128<<<agg_blocks, T>>>(m, bh + (size_t)l * DH, jk + (size_t)(l + 1) * DH, JKW);
    }

    // p = jk @ Wout (project before final aggregation, by linearity)
    k_gemm_h16<128, 64, 32, 32, 32, 3><<<gemm_blocks, T, SM64>>>(
        jk, JKW, NNODES, JKW, w16 + WOUT_OFF, p, DOUT);

    // out = bout + segsum(p[src], dst)
    k_agg64<<<agg_blocks, T>>>(p, bout, out);
}

// round 12
// speedup vs baseline: 1.5624x; 1.5624x over previous
#include <cuda_runtime.h>
#include <cuda_fp16.h>
#include <cstdint>
#include <cstddef>

#define NNODES 30000
#define NEDGES 300000
#define DIN    256
#define DH     128
#define DOUT   64
#define LH     6
#define JKW    (DH * (LH + 1))   // 896
#define NB     ((NNODES + 255) / 256)   // 118 scan blocks
#define FEATB  7500                     // NNODES*DIN/4/256: feats-convert blocks

// ---------------- scratch (device globals: no allocs allowed) ----------------
__device__ __half g_feat16[(size_t)NNODES * DIN];
__device__ __half g_m16[(size_t)NNODES * DH];
__device__ __half g_jk16[(size_t)NNODES * JKW];
__device__ __half g_p16[(size_t)NNODES * DOUT];
__device__ float g_iso[NNODES], g_isi[NNODES];
__device__ int   g_cin[NNODES], g_cout[NNODES];
__device__ int   g_rp[NNODES + 1];
__device__ int   g_scan[NNODES];
__device__ int   g_bsum[128];
__device__ int   g_cur[NNODES];
__device__ int   g_csrc[NEDGES];
// fp16 transposed weights, [N][K] each: W0t 128x256 | Wht 6x128x128 | WoutT 64x896
#define W0T_OFF   0
#define WHT_OFF   32768
#define WOUT_OFF  131072
__device__ __half g_w16[188416];

// ---------------- prep: feats fp32->fp16 + weights fp32->fp16 transposed ----
__global__ __launch_bounds__(256) void k_prep(
    const float* __restrict__ feats, const float* __restrict__ W0,
    const float* __restrict__ Wh, const float* __restrict__ Wout)
{
    int b = blockIdx.x;
    if (b < FEATB) {
        int i = b * 256 + threadIdx.x;
        float4 v = ((const float4*)feats)[i];
        ((__half2*)g_feat16)[2 * i]     = __floats2half2_rn(v.x, v.y);
        ((__half2*)g_feat16)[2 * i + 1] = __floats2half2_rn(v.z, v.w);
        return;
    }
    // weight transpose: 32x32 tiles
    __shared__ float sh[32][33];
    int bid = b - FEATB;
    const float* S; __half* D; int K, N, tk, tn;
    if (bid < 32)       { S = W0;   D = g_w16 + W0T_OFF;  K = 256; N = 128; tk = bid >> 2; tn = bid & 3; }
    else if (bid < 128) { int l = (bid - 32) >> 4, t2 = (bid - 32) & 15;
                          S = Wh + l * 16384; D = g_w16 + WHT_OFF + l * 16384;
                          K = 128; N = 128; tk = t2 >> 2; tn = t2 & 3; }
    else                { int t2 = bid - 128;
                          S = Wout; D = g_w16 + WOUT_OFF; K = 896; N = 64; tk = t2 >> 1; tn = t2 & 1; }
    int tx = threadIdx.x & 31, ty = threadIdx.x >> 5;   // 32 x 8
#pragma unroll
    for (int j = 0; j < 4; j++)
        sh[ty + j * 8][tx] = S[(size_t)(tk * 32 + ty + j * 8) * N + tn * 32 + tx];
    __syncthreads();
#pragma unroll
    for (int j = 0; j < 4; j++)
        D[(size_t)(tn * 32 + ty + j * 8) * K + tk * 32 + tx] = __float2half(sh[tx][ty + j * 8]);
}

// ---------------- CSR build ----------------
__global__ void k_hist(const int* __restrict__ src, const int* __restrict__ dst) {
    int e = blockIdx.x * blockDim.x + threadIdx.x;
    if (e < NEDGES) {
        atomicAdd(&g_cin[dst[e]], 1);
        atomicAdd(&g_cout[src[e]], 1);
    }
}

__global__ void k_scan1() {   // per-block inclusive scan of g_cin
    __shared__ int sh[256];
    int t = threadIdx.x;
    int i = blockIdx.x * 256 + t;
    int v = (i < NNODES) ? g_cin[i] : 0;
    sh[t] = v;
    __syncthreads();
    for (int o = 1; o < 256; o <<= 1) {
        int u = (t >= o) ? sh[t - o] : 0;
        __syncthreads();
        sh[t] += u;
        __syncthreads();
    }
    if (i < NNODES) g_scan[i] = sh[t];
    if (t == 255) g_bsum[blockIdx.x] = sh[255];
}

__global__ void k_scan2() {   // parallel exclusive scan of 118 block sums
    __shared__ int sh[128];
    int t = threadIdx.x;
    int v = (t < NB) ? g_bsum[t] : 0;
    sh[t] = v;
    __syncthreads();
    for (int o = 1; o < 128; o <<= 1) {
        int u = (t >= o) ? sh[t - o] : 0;
        __syncthreads();
        sh[t] += u;
        __syncthreads();
    }
    if (t < NB) g_bsum[t] = sh[t] - v;   // exclusive
}

__global__ void k_scan3() {   // fused: row pointers + cursors + rsqrt norms
    int i = blockIdx.x * blockDim.x + threadIdx.x;
    if (i < NNODES) {
        int cin = g_cin[i];
        int inc = g_scan[i] + g_bsum[i >> 8];
        g_rp[i + 1] = inc;
        if (i == 0) g_rp[0] = 0;
        g_cur[i] = inc - cin;
        g_iso[i] = rsqrtf((float)max(g_cout[i], 1));
        g_isi[i] = rsqrtf((float)max(cin, 1));
    }
}

__global__ void k_fill(const int* __restrict__ src, const int* __restrict__ dst) {
    int e = blockIdx.x * blockDim.x + threadIdx.x;
    if (e < NEDGES) {
        int pos = atomicAdd(&g_cur[dst[e]], 1);
        g_csrc[pos] = src[e];
    }
}

// ---------------- CSR aggregation, width 128 (fp16 in/out, fp32 math) -------
__global__ __launch_bounds__(256) void k_agg128(
    const __half* __restrict__ x,
    const float* __restrict__ bias,
    __half* __restrict__ out, int ldo)
{
    int w = (int)((blockIdx.x * 256u + threadIdx.x) >> 5);
    int lane = threadIdx.x & 31;
    if (w >= NNODES) return;
    int beg = g_rp[w], end = g_rp[w + 1];

    float4 acc = make_float4(0.f, 0.f, 0.f, 0.f);
    int e = beg;
    for (; e + 4 <= end; e += 4) {
        int s0 = g_csrc[e], s1 = g_csrc[e + 1], s2 = g_csrc[e + 2], s3 = g_csrc[e + 3];
        float2 r0 = __ldg((const float2*)(x + (size_t)s0 * DH) + lane);
        float2 r1 = __ldg((const float2*)(x + (size_t)s1 * DH) + lane);
        float2 r2 = __ldg((const float2*)(x + (size_t)s2 * DH) + lane);
        float2 r3 = __ldg((const float2*)(x + (size_t)s3 * DH) + lane);
        float c0 = g_iso[s0], c1 = g_iso[s1], c2 = g_iso[s2], c3 = g_iso[s3];
        float2 a0 = __half22float2(*(__half2*)&r0.x), b0 = __half22float2(*(__half2*)&r0.y);
        float2 a1 = __half22float2(*(__half2*)&r1.x), b1 = __half22float2(*(__half2*)&r1.y);
        float2 a2 = __half22float2(*(__half2*)&r2.x), b2 = __half22float2(*(__half2*)&r2.y);
        float2 a3 = __half22float2(*(__half2*)&r3.x), b3 = __half22float2(*(__half2*)&r3.y);
        acc.x += a0.x * c0 + a1.x * c1 + a2.x * c2 + a3.x * c3;
        acc.y += a0.y * c0 + a1.y * c1 + a2.y * c2 + a3.y * c3;
        acc.z += b0.x * c0 + b1.x * c1 + b2.x * c2 + b3.x * c3;
        acc.w += b0.y * c0 + b1.y * c1 + b2.y * c2 + b3.y * c3;
    }
    for (; e < end; e++) {
        int s = g_csrc[e];
        float2 r = __ldg((const float2*)(x + (size_t)s * DH) + lane);
        float c = g_iso[s];
        float2 a = __half22float2(*(__half2*)&r.x), b = __half22float2(*(__half2*)&r.y);
        acc.x += a.x * c; acc.y += a.y * c; acc.z += b.x * c; acc.w += b.y * c;
    }

    float si = g_isi[w];
    float4 b = ((const float4*)bias)[lane];
    float vx = fmaxf(acc.x * si + b.x, 0.f);
    float vy = fmaxf(acc.y * si + b.y, 0.f);
    float vz = fmaxf(acc.z * si + b.z, 0.f);
    float vw = fmaxf(acc.w * si + b.w, 0.f);
    __half2* orow = (__half2*)(out + (size_t)w * ldo);
    orow[2 * lane]     = __floats2half2_rn(vx, vy);
    orow[2 * lane + 1] = __floats2half2_rn(vz, vw);
}

__global__ __launch_bounds__(256) void k_agg64(
    const __half* __restrict__ x,
    const float* __restrict__ bias,
    float* __restrict__ out)
{
    int w = (int)((blockIdx.x * 256u + threadIdx.x) >> 5);
    int lane = threadIdx.x & 31;
    if (w >= NNODES) return;
    int beg = g_rp[w], end = g_rp[w + 1];

    float2 acc = make_float2(0.f, 0.f);
    int e = beg;
    for (; e + 4 <= end; e += 4) {
        int s0 = g_csrc[e], s1 = g_csrc[e + 1], s2 = g_csrc[e + 2], s3 = g_csrc[e + 3];
        unsigned u0 = __ldg((const unsigned*)(x + (size_t)s0 * DOUT) + lane);
        unsigned u1 = __ldg((const unsigned*)(x + (size_t)s1 * DOUT) + lane);
        unsigned u2 = __ldg((const unsigned*)(x + (size_t)s2 * DOUT) + lane);
        unsigned u3 = __ldg((const unsigned*)(x + (size_t)s3 * DOUT) + lane);
        float2 f0 = __half22float2(*(__half2*)&u0);
        float2 f1 = __half22float2(*(__half2*)&u1);
        float2 f2 = __half22float2(*(__half2*)&u2);
        float2 f3 = __half22float2(*(__half2*)&u3);
        acc.x += f0.x + f1.x + f2.x + f3.x;
        acc.y += f0.y + f1.y + f2.y + f3.y;
    }
    for (; e < end; e++) {
        int s = g_csrc[e];
        unsigned u = __ldg((const unsigned*)(x + (size_t)s * DOUT) + lane);
        float2 f = __half22float2(*(__half2*)&u);
        acc.x += f.x; acc.y += f.y;
    }
    float2 b = ((const float2*)bias)[lane];
    ((float2*)(out + (size_t)w * DOUT))[lane] = make_float2(acc.x + b.x, acc.y + b.y);
}

// -------- fp16 HMMA GEMM (m16n8k16), cp.async 3-stage pipeline ---------------
__device__ __forceinline__ void mma_f16(float* c, const unsigned* a, const unsigned* b) {
    asm volatile(
        "mma.sync.aligned.m16n8k16.row.col.f32.f16.f16.f32 "
        "{%0,%1,%2,%3}, {%4,%5,%6,%7}, {%8,%9}, {%0,%1,%2,%3};"
        : "+f"(c[0]), "+f"(c[1]), "+f"(c[2]), "+f"(c[3])
        : "r"(a[0]), "r"(a[1]), "r"(a[2]), "r"(a[3]), "r"(b[0]), "r"(b[1]));
}

__device__ __forceinline__ void cpa16(uint32_t dst, const void* src, int sz) {
    asm volatile("cp.async.cg.shared.global [%0], [%1], 16, %2;"
                 :: "r"(dst), "l"(src), "r"(sz) : "memory");
}
__device__ __forceinline__ void cpa_commit() {
    asm volatile("cp.async.commit_group;" ::: "memory");
}
template <int Nw>
__device__ __forceinline__ void cpa_wait() {
    asm volatile("cp.async.wait_group %0;" :: "n"(Nw) : "memory");
}

// C[M, BN] = A[M, K] @ Bt^T;  A fp16 [M][lda], Bt fp16 [BN][K] (K contiguous), C fp16.
template <int BM, int BN, int BK, int WM, int WN, int STAGES>
__global__ __launch_bounds__(256) void k_gemm_h16(
    const __half* __restrict__ A, int lda, int M, int K,
    const __half* __restrict__ Bt,
    __half* __restrict__ C, int ldc)
{
    constexpr int ASH = BK + 8;    // halves; 80B row stride -> conflict-free frags
    constexpr int BSH = BK + 8;
    extern __shared__ char smraw[];
    __half* Asm = (__half*)smraw;                                   // STAGES*BM*ASH
    __half* Bsm = (__half*)(smraw + (size_t)STAGES * BM * ASH * 2); // STAGES*BN*BSH
    const uint32_t sA = (uint32_t)__cvta_generic_to_shared(Asm);
    const uint32_t sB = (uint32_t)__cvta_generic_to_shared(Bsm);

    constexpr int WARPS_N = BN / WN;
    static_assert((BM / WM) * WARPS_N == 8, "8 warps");
    constexpr int MT = WM / 16, NT = WN / 8;
    constexpr int KC = BK / 8;                  // 16B half-chunks per row
    constexpr int A_PT = BM * KC / 256;
    constexpr int B_PT = BN * KC / 256;

    const int tid = threadIdx.x;
    const int wid = tid >> 5, lane = tid & 31;
    const int wn = wid % WARPS_N, wm = wid / WARPS_N;
    const int g = lane >> 2, t = lane & 3;
    const int row0 = blockIdx.x * BM;
    const int S = K / BK;

    auto prefetch = [&](int s, int slot) {
        const int k0 = s * BK;
#pragma unroll
        for (int i = 0; i < A_PT; i++) {
            int id = tid + i * 256;
            int r = id / KC, q = id % KC;
            int gr = row0 + r;
            uint32_t d = sA + ((slot * BM + r) * ASH + q * 8) * 2;
            cpa16(d, A + (size_t)gr * lda + k0 + q * 8, (gr < M) ? 16 : 0);
        }
#pragma unroll
        for (int i = 0; i < B_PT; i++) {
            int id = tid + i * 256;
            int r = id / KC, q = id % KC;
            uint32_t d = sB + ((slot * BN + r) * BSH + q * 8) * 2;
            cpa16(d, Bt + (size_t)r * K + k0 + q * 8, 16);
        }
        cpa_commit();
    };

    float acc[MT][NT][4] = {};

#pragma unroll
    for (int s = 0; s < STAGES - 1; s++) prefetch(s, s);

#pragma unroll 1
    for (int s = 0; s < S; s++) {
        cpa_wait<STAGES - 2>();
        __syncthreads();

        int sn = s + STAGES - 1;
        if (sn < S) prefetch(sn, sn % STAGES);
        else        cpa_commit();

        const int slot = s % STAGES;
        const __half* Aslab = Asm + (size_t)slot * BM * ASH;
        const __half* Bslab = Bsm + (size_t)slot * BN * BSH;
#pragma unroll
        for (int ks = 0; ks < BK / 16; ks++) {
            unsigned a[MT][4], b[NT][2];
#pragma unroll
            for (int mt = 0; mt < MT; mt++) {
                const __half* ap = &Aslab[(wm * WM + mt * 16 + g) * ASH + ks * 16 + 2 * t];
                a[mt][0] = *(const unsigned*)(ap);
                a[mt][1] = *(const unsigned*)(ap + 8 * ASH);
                a[mt][2] = *(const unsigned*)(ap + 8);
                a[mt][3] = *(const unsigned*)(ap + 8 * ASH + 8);
            }
#pragma unroll
            for (int nt = 0; nt < NT; nt++) {
                const __half* bp = &Bslab[(wn * WN + nt * 8 + g) * BSH + ks * 16 + 2 * t];
                b[nt][0] = *(const unsigned*)(bp);
                b[nt][1] = *(const unsigned*)(bp + 8);
            }
#pragma unroll
            for (int mt = 0; mt < MT; mt++)
#pragma unroll
                for (int nt = 0; nt < NT; nt++)
                    mma_f16(acc[mt][nt], a[mt], b[nt]);
        }
    }

    // epilogue: half2 stores (bias/relu live in the agg kernels)
#pragma unroll
    for (int mt = 0; mt < MT; mt++) {
#pragma unroll
        for (int nt = 0; nt < NT; nt++) {
            int n = wn * WN + nt * 8 + 2 * t;
            int r0 = row0 + wm * WM + mt * 16 + g;
            if (r0 < M)
                *(__half2*)(C + (size_t)r0 * ldc + n) =
                    __floats2half2_rn(acc[mt][nt][0], acc[mt][nt][1]);
            int r1 = r0 + 8;
            if (r1 < M)
                *(__half2*)(C + (size_t)r1 * ldc + n) =
                    __floats2half2_rn(acc[mt][nt][2], acc[mt][nt][3]);
        }
    }
}

// ---------------- launch ----------------
extern "C" void kernel_launch(void* const* d_in, const int* in_sizes, int n_in,
                              void* d_out, int out_size)
{
    const float* feats = (const float*)d_in[0];
    const int*   src   = (const int*)d_in[1];
    const int*   dst   = (const int*)d_in[2];
    const float* W0    = (const float*)d_in[3];
    const float* b0    = (const float*)d_in[4];
    const float* Wh    = (const float*)d_in[5];
    const float* bh    = (const float*)d_in[6];
    const float* Wout  = (const float*)d_in[7];
    const float* bout  = (const float*)d_in[8];
    float* out = (float*)d_out;

    __half *f16, *m, *jk, *p, *w16;
    int *cin, *cout;
    cudaGetSymbolAddress((void**)&f16,  g_feat16);
    cudaGetSymbolAddress((void**)&m,    g_m16);
    cudaGetSymbolAddress((void**)&jk,   g_jk16);
    cudaGetSymbolAddress((void**)&p,    g_p16);
    cudaGetSymbolAddress((void**)&w16,  g_w16);
    cudaGetSymbolAddress((void**)&cin,  g_cin);
    cudaGetSymbolAddress((void**)&cout, g_cout);

    // dynamic smem: STAGES * (BM + BN) * (BK+8) * 2 bytes
    const int SM128 = 3 * (128 + 128) * 40 * 2;   // 61440
    const int SM64  = 3 * (128 + 64)  * 40 * 2;   // 46080
    cudaFuncSetAttribute((const void*)k_gemm_h16<128, 128, 32, 64, 32, 3>,
                         cudaFuncAttributeMaxDynamicSharedMemorySize, SM128);
    cudaFuncSetAttribute((const void*)k_gemm_h16<128, 64, 32, 32, 32, 3>,
                         cudaFuncAttributeMaxDynamicSharedMemorySize, SM64);

    const int T = 256;
    const int eb = (NEDGES + T - 1) / T;
    const int agg_blocks = (NNODES * 32 + T - 1) / T;
    const int gemm_blocks = (NNODES + 127) / 128;   // 235

    // CSR build + fp16 prep
    cudaMemsetAsync(cin,  0, NNODES * sizeof(int));
    cudaMemsetAsync(cout, 0, NNODES * sizeof(int));
    k_prep<<<FEATB + 184, T>>>(feats, W0, Wh, Wout);
    k_hist<<<eb, T>>>(src, dst);
    k_scan1<<<NB, T>>>();
    k_scan2<<<1, 128>>>();
    k_scan3<<<NB, T>>>();
    k_fill<<<eb, T>>>(src, dst);

    // layer 0 (GEMM-first: project feats, then aggregate at width 128)
    k_gemm_h16<128, 128, 32, 64, 32, 3><<<gemm_blocks, T, SM128>>>(
        f16, DIN, NNODES, DIN, w16 + W0T_OFF, m, DH);
    k_agg128<<<agg_blocks, T>>>(m, b0, jk, JKW);

    // hidden layers 1..6
    for (int l = 0; l < LH; l++) {
        k_gemm_h16<128, 128, 32, 64, 32, 3><<<gemm_blocks, T, SM128>>>(
            jk + (size_t)l * DH, JKW, NNODES, DH, w16 + WHT_OFF + (size_t)l * DH * DH, m, DH);
        k_agg128<<<agg_blocks, T>>>(m, bh + (size_t)l * DH, jk + (size_t)(l + 1) * DH, JKW);
    }

    // p = jk @ Wout (project before final aggregation, by linearity)
    k_gemm_h16<128, 64, 32, 32, 32, 3><<<gemm_blocks, T, SM64>>>(
        jk, JKW, NNODES, JKW, w16 + WOUT_OFF, p, DOUT);

    // out = bout + segsum(p[src], dst)
    k_agg64<<<agg_blocks, T>>>(p, bout, out);
}

// round 13
// speedup vs baseline: 1.6858x; 1.0790x over previous
#include <cuda_runtime.h>
#include <cuda_fp16.h>
#include <cstdint>
#include <cstddef>

#define NNODES 30000
#define NEDGES 300000
#define DIN    256
#define DH     128
#define DOUT   64
#define LH     6
#define JKW    (DH * (LH + 1))   // 896
#define NB     ((NNODES + 255) / 256)   // 118 scan blocks

// ---------------- scratch (device globals: no allocs allowed) ----------------
__device__ __half g_m16[(size_t)NNODES * DH];
__device__ __half g_jk16[(size_t)NNODES * JKW];
__device__ __half g_p16[(size_t)NNODES * DOUT];
__device__ float g_iso[NNODES], g_isi[NNODES];
__device__ int   g_cin[NNODES], g_cout[NNODES];
__device__ int   g_rp[NNODES + 1];
__device__ int   g_scan[NNODES];
__device__ int   g_bsum[128];
__device__ int   g_cur[NNODES];
__device__ int   g_csrc[NEDGES];
// fp16 transposed weights, [N][K] each: W0t 128x256 | Wht 6x128x128 | WoutT 64x896
#define W0T_OFF   0
#define WHT_OFF   32768
#define WOUT_OFF  131072
__device__ __half g_w16[188416];

// ---------------- prep: weights fp32 -> fp16 transposed ----------------------
__global__ __launch_bounds__(256) void k_prep(
    const float* __restrict__ W0, const float* __restrict__ Wh,
    const float* __restrict__ Wout)
{
    __shared__ float sh[32][33];
    int bid = blockIdx.x;
    const float* S; __half* D; int K, N, tk, tn;
    if (bid < 32)       { S = W0;   D = g_w16 + W0T_OFF;  K = 256; N = 128; tk = bid >> 2; tn = bid & 3; }
    else if (bid < 128) { int l = (bid - 32) >> 4, t2 = (bid - 32) & 15;
                          S = Wh + l * 16384; D = g_w16 + WHT_OFF + l * 16384;
                          K = 128; N = 128; tk = t2 >> 2; tn = t2 & 3; }
    else                { int t2 = bid - 128;
                          S = Wout; D = g_w16 + WOUT_OFF; K = 896; N = 64; tk = t2 >> 1; tn = t2 & 1; }
    int tx = threadIdx.x & 31, ty = threadIdx.x >> 5;   // 32 x 8
#pragma unroll
    for (int j = 0; j < 4; j++)
        sh[ty + j * 8][tx] = S[(size_t)(tk * 32 + ty + j * 8) * N + tn * 32 + tx];
    __syncthreads();
#pragma unroll
    for (int j = 0; j < 4; j++)
        D[(size_t)(tn * 32 + ty + j * 8) * K + tk * 32 + tx] = __float2half(sh[tx][ty + j * 8]);
}

// ---------------- CSR build ----------------
__global__ void k_hist(const int* __restrict__ src, const int* __restrict__ dst) {
    int e = blockIdx.x * blockDim.x + threadIdx.x;
    if (e < NEDGES) {
        atomicAdd(&g_cin[dst[e]], 1);
        atomicAdd(&g_cout[src[e]], 1);
    }
}

__global__ void k_scan1() {   // per-block inclusive scan of g_cin
    __shared__ int sh[256];
    int t = threadIdx.x;
    int i = blockIdx.x * 256 + t;
    int v = (i < NNODES) ? g_cin[i] : 0;
    sh[t] = v;
    __syncthreads();
    for (int o = 1; o < 256; o <<= 1) {
        int u = (t >= o) ? sh[t - o] : 0;
        __syncthreads();
        sh[t] += u;
        __syncthreads();
    }
    if (i < NNODES) g_scan[i] = sh[t];
    if (t == 255) g_bsum[blockIdx.x] = sh[255];
}

__global__ __launch_bounds__(256) void k_scan3() {
    // per-block: offset = sum of bsum[0..b-1] (warp reduce), then rp/cur/rsqrt
    __shared__ int soff;
    int b = blockIdx.x, t = threadIdx.x;
    if (t < 32) {
        int s = 0;
        for (int j = t; j < b; j += 32) s += g_bsum[j];   // <= 4 iters
#pragma unroll
        for (int o = 16; o; o >>= 1) s += __shfl_down_sync(0xffffffffu, s, o);
        if (t == 0) soff = s;
    }
    __syncthreads();
    int i = b * 256 + t;
    if (i < NNODES) {
        int cin = g_cin[i];
        int inc = g_scan[i] + soff;
        g_rp[i + 1] = inc;
        if (i == 0) g_rp[0] = 0;
        g_cur[i] = inc - cin;
        g_iso[i] = rsqrtf((float)max(g_cout[i], 1));
        g_isi[i] = rsqrtf((float)max(cin, 1));
    }
}

__global__ void k_fill(const int* __restrict__ src, const int* __restrict__ dst) {
    int e = blockIdx.x * blockDim.x + threadIdx.x;
    if (e < NEDGES) {
        int pos = atomicAdd(&g_cur[dst[e]], 1);
        g_csrc[pos] = src[e];
    }
}

// ---------------- CSR aggregation, width 128 (fp16 in/out, fp32 math) -------
// EDGEISO: multiply each gathered row by iso[s] (layer 0 only; hidden layers
// have iso pre-folded into the GEMM epilogue).
template <bool EDGEISO>
__global__ __launch_bounds__(256) void k_agg128(
    const __half* __restrict__ x,
    const float* __restrict__ bias,
    __half* __restrict__ out, int ldo)
{
    int w = (int)((blockIdx.x * 256u + threadIdx.x) >> 5);
    int lane = threadIdx.x & 31;
    if (w >= NNODES) return;
    int beg = g_rp[w], end = g_rp[w + 1];

    float4 acc = make_float4(0.f, 0.f, 0.f, 0.f);
    int e = beg;
    for (; e + 4 <= end; e += 4) {
        int s0 = g_csrc[e], s1 = g_csrc[e + 1], s2 = g_csrc[e + 2], s3 = g_csrc[e + 3];
        float2 r0 = __ldg((const float2*)(x + (size_t)s0 * DH) + lane);
        float2 r1 = __ldg((const float2*)(x + (size_t)s1 * DH) + lane);
        float2 r2 = __ldg((const float2*)(x + (size_t)s2 * DH) + lane);
        float2 r3 = __ldg((const float2*)(x + (size_t)s3 * DH) + lane);
        float2 a0 = __half22float2(*(__half2*)&r0.x), b0 = __half22float2(*(__half2*)&r0.y);
        float2 a1 = __half22float2(*(__half2*)&r1.x), b1 = __half22float2(*(__half2*)&r1.y);
        float2 a2 = __half22float2(*(__half2*)&r2.x), b2 = __half22float2(*(__half2*)&r2.y);
        float2 a3 = __half22float2(*(__half2*)&r3.x), b3 = __half22float2(*(__half2*)&r3.y);
        if (EDGEISO) {
            float c0 = g_iso[s0], c1 = g_iso[s1], c2 = g_iso[s2], c3 = g_iso[s3];
            acc.x += a0.x * c0 + a1.x * c1 + a2.x * c2 + a3.x * c3;
            acc.y += a0.y * c0 + a1.y * c1 + a2.y * c2 + a3.y * c3;
            acc.z += b0.x * c0 + b1.x * c1 + b2.x * c2 + b3.x * c3;
            acc.w += b0.y * c0 + b1.y * c1 + b2.y * c2 + b3.y * c3;
        } else {
            acc.x += (a0.x + a1.x) + (a2.x + a3.x);
            acc.y += (a0.y + a1.y) + (a2.y + a3.y);
            acc.z += (b0.x + b1.x) + (b2.x + b3.x);
            acc.w += (b0.y + b1.y) + (b2.y + b3.y);
        }
    }
    for (; e < end; e++) {
        int s = g_csrc[e];
        float2 r = __ldg((const float2*)(x + (size_t)s * DH) + lane);
        float2 a = __half22float2(*(__half2*)&r.x), b = __half22float2(*(__half2*)&r.y);
        float c = EDGEISO ? g_iso[s] : 1.f;
        acc.x += a.x * c; acc.y += a.y * c; acc.z += b.x * c; acc.w += b.y * c;
    }

    float si = g_isi[w];
    float4 b = ((const float4*)bias)[lane];
    float vx = fmaxf(acc.x * si + b.x, 0.f);
    float vy = fmaxf(acc.y * si + b.y, 0.f);
    float vz = fmaxf(acc.z * si + b.z, 0.f);
    float vw = fmaxf(acc.w * si + b.w, 0.f);
    __half2* orow = (__half2*)(out + (size_t)w * ldo);
    orow[2 * lane]     = __floats2half2_rn(vx, vy);
    orow[2 * lane + 1] = __floats2half2_rn(vz, vw);
}

__global__ __launch_bounds__(256) void k_agg64(
    const __half* __restrict__ x,
    const float* __restrict__ bias,
    float* __restrict__ out)
{
    int w = (int)((blockIdx.x * 256u + threadIdx.x) >> 5);
    int lane = threadIdx.x & 31;
    if (w >= NNODES) return;
    int beg = g_rp[w], end = g_rp[w + 1];

    float2 acc = make_float2(0.f, 0.f);
    int e = beg;
    for (; e + 4 <= end; e += 4) {
        int s0 = g_csrc[e], s1 = g_csrc[e + 1], s2 = g_csrc[e + 2], s3 = g_csrc[e + 3];
        unsigned u0 = __ldg((const unsigned*)(x + (size_t)s0 * DOUT) + lane);
        unsigned u1 = __ldg((const unsigned*)(x + (size_t)s1 * DOUT) + lane);
        unsigned u2 = __ldg((const unsigned*)(x + (size_t)s2 * DOUT) + lane);
        unsigned u3 = __ldg((const unsigned*)(x + (size_t)s3 * DOUT) + lane);
        float2 f0 = __half22float2(*(__half2*)&u0);
        float2 f1 = __half22float2(*(__half2*)&u1);
        float2 f2 = __half22float2(*(__half2*)&u2);
        float2 f3 = __half22float2(*(__half2*)&u3);
        acc.x += (f0.x + f1.x) + (f2.x + f3.x);
        acc.y += (f0.y + f1.y) + (f2.y + f3.y);
    }
    for (; e < end; e++) {
        int s = g_csrc[e];
        unsigned u = __ldg((const unsigned*)(x + (size_t)s * DOUT) + lane);
        float2 f = __half22float2(*(__half2*)&u);
        acc.x += f.x; acc.y += f.y;
    }
    float2 b = ((const float2*)bias)[lane];
    ((float2*)(out + (size_t)w * DOUT))[lane] = make_float2(acc.x + b.x, acc.y + b.y);
}

// -------- fp16 HMMA GEMM (m16n8k16), cp.async 3-stage pipeline ---------------
// AF32: A operand is fp32 in gmem/smem, converted to fp16 at fragment load.
// SCALE: multiply output rows by rowscale[] (iso fold) before fp16 store.
__device__ __forceinline__ void mma_f16(float* c, const unsigned* a, const unsigned* b) {
    asm volatile(
        "mma.sync.aligned.m16n8k16.row.col.f32.f16.f16.f32 "
        "{%0,%1,%2,%3}, {%4,%5,%6,%7}, {%8,%9}, {%0,%1,%2,%3};"
        : "+f"(c[0]), "+f"(c[1]), "+f"(c[2]), "+f"(c[3])
        : "r"(a[0]), "r"(a[1]), "r"(a[2]), "r"(a[3]), "r"(b[0]), "r"(b[1]));
}

__device__ __forceinline__ void cpa16(uint32_t dst, const void* src, int sz) {
    asm volatile("cp.async.cg.shared.global [%0], [%1], 16, %2;"
                 :: "r"(dst), "l"(src), "r"(sz) : "memory");
}
__device__ __forceinline__ void cpa_commit() {
    asm volatile("cp.async.commit_group;" ::: "memory");
}
template <int Nw>
__device__ __forceinline__ void cpa_wait() {
    asm volatile("cp.async.wait_group %0;" :: "n"(Nw) : "memory");
}

__device__ __forceinline__ unsigned packh2(float x, float y) {
    __half2 h = __floats2half2_rn(x, y);
    return *(unsigned*)&h;
}

template <int BM, int BN, int BK, int WM, int WN, int STAGES, bool AF32, bool SCALE>
__global__ __launch_bounds__(256) void k_gemm(
    const void* __restrict__ Avoid, int lda, int M, int K,
    const __half* __restrict__ Bt,            // [BN-col-major: [N][K] fp16]
    const float* __restrict__ rowscale,
    __half* __restrict__ C, int ldc)
{
    constexpr int ASH = BK + 8;    // halves (fp16 A path): 80B stride, conflict-free
    constexpr int ASF = BK + 4;    // floats (fp32 A path): 144B stride, 2-way on .64
    constexpr int BSH = BK + 8;
    constexpr int A_SLAB_BYTES = AF32 ? BM * ASF * 4 : BM * ASH * 2;
    extern __shared__ char smraw[];
    char* Abase = smraw;
    __half* Bsm = (__half*)(smraw + (size_t)STAGES * A_SLAB_BYTES);
    const uint32_t sA = (uint32_t)__cvta_generic_to_shared(Abase);
    const uint32_t sB = (uint32_t)__cvta_generic_to_shared(Bsm);

    constexpr int WARPS_N = BN / WN;
    static_assert((BM / WM) * WARPS_N == 8, "8 warps");
    constexpr int MT = WM / 16, NT = WN / 8;
    constexpr int KC  = BK / 8;                 // fp16: 16B chunks per row
    constexpr int KCF = BK / 4;                 // fp32: 16B chunks per row
    constexpr int A_PT = AF32 ? (BM * KCF / 256) : (BM * KC / 256);
    constexpr int B_PT = BN * KC / 256;

    const int tid = threadIdx.x;
    const int wid = tid >> 5, lane = tid & 31;
    const int wn = wid % WARPS_N, wm = wid / WARPS_N;
    const int g = lane >> 2, t = lane & 3;
    const int row0 = blockIdx.x * BM;
    const int S = K / BK;

    auto prefetch = [&](int s, int slot) {
        const int k0 = s * BK;
        if (AF32) {
            const float* Af = (const float*)Avoid;
#pragma unroll
            for (int i = 0; i < A_PT; i++) {
                int id = tid + i * 256;
                int r = id / KCF, q = id % KCF;
                int gr = row0 + r;
                uint32_t d = sA + (uint32_t)slot * A_SLAB_BYTES + (r * ASF + q * 4) * 4;
                cpa16(d, Af + (size_t)gr * lda + k0 + q * 4, (gr < M) ? 16 : 0);
            }
        } else {
            const __half* Ah = (const __half*)Avoid;
#pragma unroll
            for (int i = 0; i < A_PT; i++) {
                int id = tid + i * 256;
                int r = id / KC, q = id % KC;
                int gr = row0 + r;
                uint32_t d = sA + (uint32_t)slot * A_SLAB_BYTES + (r * ASH + q * 8) * 2;
                cpa16(d, Ah + (size_t)gr * lda + k0 + q * 8, (gr < M) ? 16 : 0);
            }
        }
#pragma unroll
        for (int i = 0; i < B_PT; i++) {
            int id = tid + i * 256;
            int r = id / KC, q = id % KC;
            uint32_t d = sB + ((slot * BN + r) * BSH + q * 8) * 2;
            cpa16(d, Bt + (size_t)r * K + k0 + q * 8, 16);
        }
        cpa_commit();
    };

    float acc[MT][NT][4] = {};

#pragma unroll
    for (int s = 0; s < STAGES - 1; s++) prefetch(s, s);

#pragma unroll 1
    for (int s = 0; s < S; s++) {
        cpa_wait<STAGES - 2>();
        __syncthreads();

        int sn = s + STAGES - 1;
        if (sn < S) prefetch(sn, sn % STAGES);
        else        cpa_commit();

        const int slot = s % STAGES;
        const __half* Bslab = Bsm + (size_t)slot * BN * BSH;
#pragma unroll
        for (int ks = 0; ks < BK / 16; ks++) {
            unsigned a[MT][4], b[NT][2];
            if (AF32) {
                const float* Aslab = (const float*)(Abase + (size_t)slot * A_SLAB_BYTES);
#pragma unroll
                for (int mt = 0; mt < MT; mt++) {
                    const float* ap = &Aslab[(wm * WM + mt * 16 + g) * ASF + ks * 16 + 2 * t];
                    float2 v0 = *(const float2*)(ap);
                    float2 v1 = *(const float2*)(ap + 8 * ASF);
                    float2 v2 = *(const float2*)(ap + 8);
                    float2 v3 = *(const float2*)(ap + 8 * ASF + 8);
                    a[mt][0] = packh2(v0.x, v0.y);
                    a[mt][1] = packh2(v1.x, v1.y);
                    a[mt][2] = packh2(v2.x, v2.y);
                    a[mt][3] = packh2(v3.x, v3.y);
                }
            } else {
                const __half* Aslab = (const __half*)(Abase + (size_t)slot * A_SLAB_BYTES);
#pragma unroll
                for (int mt = 0; mt < MT; mt++) {
                    const __half* ap = &Aslab[(wm * WM + mt * 16 + g) * ASH + ks * 16 + 2 * t];
                    a[mt][0] = *(const unsigned*)(ap);
                    a[mt][1] = *(const unsigned*)(ap + 8 * ASH);
                    a[mt][2] = *(const unsigned*)(ap + 8);
                    a[mt][3] = *(const unsigned*)(ap + 8 * ASH + 8);
                }
            }
#pragma unroll
            for (int nt = 0; nt < NT; nt++) {
                const __half* bp = &Bslab[(wn * WN + nt * 8 + g) * BSH + ks * 16 + 2 * t];
                b[nt][0] = *(const unsigned*)(bp);
                b[nt][1] = *(const unsigned*)(bp + 8);
            }
#pragma unroll
            for (int mt = 0; mt < MT; mt++)
#pragma unroll
                for (int nt = 0; nt < NT; nt++)
                    mma_f16(acc[mt][nt], a[mt], b[nt]);
        }
    }

    // epilogue: optional rowscale (iso fold), half2 stores
#pragma unroll
    for (int mt = 0; mt < MT; mt++) {
        int r0 = row0 + wm * WM + mt * 16 + g;
        int r1 = r0 + 8;
        float s0 = 1.f, s1 = 1.f;
        if (SCALE) {
            if (r0 < M) s0 = rowscale[r0];
            if (r1 < M) s1 = rowscale[r1];
        }
#pragma unroll
        for (int nt = 0; nt < NT; nt++) {
            int n = wn * WN + nt * 8 + 2 * t;
            if (r0 < M)
                *(__half2*)(C + (size_t)r0 * ldc + n) =
                    __floats2half2_rn(acc[mt][nt][0] * s0, acc[mt][nt][1] * s0);
            if (r1 < M)
                *(__half2*)(C + (size_t)r1 * ldc + n) =
                    __floats2half2_rn(acc[mt][nt][2] * s1, acc[mt][nt][3] * s1);
        }
    }
}

// ---------------- launch ----------------
extern "C" void kernel_launch(void* const* d_in, const int* in_sizes, int n_in,
                              void* d_out, int out_size)
{
    const float* feats = (const float*)d_in[0];
    const int*   src   = (const int*)d_in[1];
    const int*   dst   = (const int*)d_in[2];
    const float* W0    = (const float*)d_in[3];
    const float* b0    = (const float*)d_in[4];
    const float* Wh    = (const float*)d_in[5];
    const float* bh    = (const float*)d_in[6];
    const float* Wout  = (const float*)d_in[7];
    const float* bout  = (const float*)d_in[8];
    float* out = (float*)d_out;

    __half *m, *jk, *p, *w16;
    float *iso;
    int *cin, *cout;
    cudaGetSymbolAddress((void**)&m,    g_m16);
    cudaGetSymbolAddress((void**)&jk,   g_jk16);
    cudaGetSymbolAddress((void**)&p,    g_p16);
    cudaGetSymbolAddress((void**)&w16,  g_w16);
    cudaGetSymbolAddress((void**)&iso,  g_iso);
    cudaGetSymbolAddress((void**)&cin,  g_cin);
    cudaGetSymbolAddress((void**)&cout, g_cout);

    // one-time stream/event objects (host-side; created on first call)
    static cudaStream_t s2 = nullptr;
    static cudaEvent_t ev0 = nullptr, ev1 = nullptr;
    if (!s2) {
        if (cudaStreamCreateWithFlags(&s2, cudaStreamNonBlocking) != cudaSuccess) s2 = nullptr;
        cudaEventCreateWithFlags(&ev0, cudaEventDisableTiming);
        cudaEventCreateWithFlags(&ev1, cudaEventDisableTiming);
    }

    const int SMH  = 3 * (128 + 128) * 40 * 2;              // fp16 A, BN=128: 61440
    const int SMHF = 3 * (128 * 36 * 4 + 128 * 40 * 2);     // fp32 A, BN=128: 85760? -> compute
    const int SM64 = 3 * (128 + 64) * 40 * 2;               // fp16 A, BN=64: 46080
    cudaFuncSetAttribute((const void*)k_gemm<128, 128, 32, 64, 32, 3, false, true>,
                         cudaFuncAttributeMaxDynamicSharedMemorySize, SMH);
    cudaFuncSetAttribute((const void*)k_gemm<128, 128, 32, 64, 32, 3, true, false>,
                         cudaFuncAttributeMaxDynamicSharedMemorySize, SMHF);
    cudaFuncSetAttribute((const void*)k_gemm<128, 64, 32, 32, 32, 3, false, false>,
                         cudaFuncAttributeMaxDynamicSharedMemorySize, SM64);

    const int T = 256;
    const int eb = (NEDGES + T - 1) / T;
    const int agg_blocks = (NNODES * 32 + T - 1) / T;
    const int gemm_blocks = (NNODES + 127) / 128;   // 235

    // ---- fork: CSR build on s2, prep+gemm0 on main ----
    cudaStream_t cs = s2 ? s2 : (cudaStream_t)0;
    if (s2) { cudaEventRecord(ev0, 0); cudaStreamWaitEvent(cs, ev0, 0); }
    cudaMemsetAsync(cin,  0, NNODES * sizeof(int), cs);
    cudaMemsetAsync(cout, 0, NNODES * sizeof(int), cs);
    k_hist<<<eb, T, 0, cs>>>(src, dst);
    k_scan1<<<NB, T, 0, cs>>>();
    k_scan3<<<NB, T, 0, cs>>>();
    k_fill<<<eb, T, 0, cs>>>(src, dst);
    if (s2) cudaEventRecord(ev1, cs);

    k_prep<<<184, T>>>(W0, Wh, Wout);
    // layer-0 GEMM: fp32 A (feats) read directly, no iso scale (iso not ready)
    k_gemm<128, 128, 32, 64, 32, 3, true, false><<<gemm_blocks, T, SMHF>>>(
        feats, DIN, NNODES, DIN, w16 + W0T_OFF, nullptr, m, DH);

    if (s2) cudaStreamWaitEvent((cudaStream_t)0, ev1, 0);

    // layer-0 aggregation (edge-side iso)
    k_agg128<true><<<agg_blocks, T>>>(m, b0, jk, JKW);

    // hidden layers 1..6 (iso folded into GEMM epilogue; agg is a pure sum)
    for (int l = 0; l < LH; l++) {
        k_gemm<128, 128, 32, 64, 32, 3, false, true><<<gemm_blocks, T, SMH>>>(
            jk + (size_t)l * DH, JKW, NNODES, DH, w16 + WHT_OFF + (size_t)l * DH * DH,
            iso, m, DH);
        k_agg128<false><<<agg_blocks, T>>>(m, bh + (size_t)l * DH, jk + (size_t)(l + 1) * DH, JKW);
    }

    // p = jk @ Wout (no scale; final agg is un-normalized)
    k_gemm<128, 64, 32, 32, 32, 3, false, false><<<gemm_blocks, T, SM64>>>(
        jk, JKW, NNODES, JKW, w16 + WOUT_OFF, nullptr, p, DOUT);

    // out = bout + segsum(p[src], dst)
    k_agg64<<<agg_blocks, T>>>(p, bout, out);
}